// round 14
// baseline (speedup 1.0000x reference)
#include <cuda_runtime.h>
#include <cuda_fp16.h>
#include <cstdint>

#define NUM_REL_MAX   20000
#define NUM_EDGES_MAX 640000
#define DIM           128
#define NUM_HEAD      8
#define NEG_SLOPE     0.2f
#define FS_T          1024
#define FS_CH         20          // FS_T * FS_CH >= NUM_REL_MAX

// Scratch (device globals -- no allocation allowed)
__device__ float  g_A[NUM_REL_MAX * DIM];          // emb @ W1^T + attn_bias (fp32)
// Interleaved fp16 table: per relation row of 256 halves (512 B).
// Quad q at byte offset q*16: [B[4q..4q+3] | MSG[4q..4q+3]]
__device__ __half g_BM[NUM_REL_MAX * 2 * DIM];
__device__ __half g_embH[NUM_REL_MAX * DIM];       // emb hi (fp16)
__device__ __half g_embL[NUM_REL_MAX * DIM];       // emb lo (fp16 residual)
__device__ __half g_WH[384 * DIM];                 // combined weights hi
__device__ __half g_WL[384 * DIM];                 // combined weights lo
__device__ int    g_cnt[NUM_REL_MAX];              // zero-initialized; re-zeroed by fullscan
__device__ int    g_off[NUM_REL_MAX + 1];
__device__ int    g_pos[NUM_REL_MAX];
__device__ unsigned int g_rec[NUM_EDGES_MAX];      // packed (bin<<16)|tail
__device__ int    g_is64;

__device__ __forceinline__ float leaky(float x) {
    return x >= 0.0f ? x : NEG_SLOPE * x;
}

// ---------------------------------------------------------------------------
// hi/lo fp16 split of emb (once; GEMM mainloop then has no conversions).
// ---------------------------------------------------------------------------
__global__ __launch_bounds__(256) void conv_emb_kernel(const float* __restrict__ emb, int n) {
    for (int i = blockIdx.x * blockDim.x + threadIdx.x; i < n;
         i += gridDim.x * blockDim.x) {
        float x = emb[i];
        __half h = __float2half(x);
        g_embH[i] = h;
        g_embL[i] = __float2half(x - __half2float(h));
    }
}

// Combined weight matrix Wc[384][128] hi/lo.
__global__ __launch_bounds__(256) void conv_w_kernel(
    const float* __restrict__ attn_w, const float* __restrict__ aggr_w) {
    int idx = blockIdx.x * blockDim.x + threadIdx.x;
    if (idx >= 384 * DIM) return;
    int r = idx >> 7, c = idx & 127;
    float x = (r < 128)  ? attn_w[r * 256 + c]
            : (r < 256)  ? attn_w[(r - 128) * 256 + 128 + c]
                         : aggr_w[(r - 256) * 128 + c];
    __half h = __float2half(x);
    g_WH[idx] = h;
    g_WL[idx] = __float2half(x - __half2float(h));
}

// ---------------------------------------------------------------------------
// Per-block dtype sniff: int64 triplets (values < 2^31) have zero odd words.
// ---------------------------------------------------------------------------
__device__ __forceinline__ int sniff_is64(const unsigned int* trip_w) {
    unsigned int w = 0;
    int lane = threadIdx.x & 31;
    if (threadIdx.x < 32) w = trip_w[1 + 2 * lane];   // odd words 1..63
    unsigned int ball = __ballot_sync(0xFFFFFFFFu, w != 0u);
    return ball == 0u;   // valid in warp 0
}

// ---------------------------------------------------------------------------
// Histogram of head indices (dtype detected in-kernel; block 0 publishes it).
// g_cnt must be zero on entry (static init / re-zeroed by fullscan).
// ---------------------------------------------------------------------------
__global__ __launch_bounds__(256) void hist_kernel(const void* __restrict__ trip, int E) {
    __shared__ int s_is64;
    int is64w = sniff_is64((const unsigned int*)trip);
    if (threadIdx.x == 0) {
        s_is64 = is64w;
        if (blockIdx.x == 0) g_is64 = is64w;
    }
    __syncthreads();
    const int* p = (const int*)trip;
    int stride = s_is64 ? 6 : 3;
    for (long e = blockIdx.x * blockDim.x + threadIdx.x; e < E;
         e += (long)gridDim.x * blockDim.x) {
        int h = p[e * stride];
        atomicAdd(&g_cnt[h], 1);
    }
}

// ---------------------------------------------------------------------------
// Single-block full exclusive scan (1024 threads x 20 counts, high MLP).
// Also re-zeroes g_cnt for the next graph replay (read-then-clear).
// ---------------------------------------------------------------------------
__global__ __launch_bounds__(FS_T) void fullscan_kernel(int M) {
    __shared__ int wsum[FS_T / 32];
    int tid = threadIdx.x;
    int lane = tid & 31;
    int wid = tid >> 5;
    int base = tid * FS_CH;

    int c[FS_CH];
    #pragma unroll
    for (int j = 0; j < FS_CH; j++) {
        int i = base + j;
        c[j] = (i < M) ? g_cnt[i] : 0;
    }
    int local = 0;
    #pragma unroll
    for (int j = 0; j < FS_CH; j++) local += c[j];

    // warp inclusive scan of per-thread sums
    int x = local;
    #pragma unroll
    for (int s = 1; s < 32; s <<= 1) {
        int y = __shfl_up_sync(0xFFFFFFFFu, x, s);
        if (lane >= s) x += y;
    }
    if (lane == 31) wsum[wid] = x;
    __syncthreads();
    if (wid == 0) {
        int w = (lane < FS_T / 32) ? wsum[lane] : 0;
        #pragma unroll
        for (int s = 1; s < FS_T / 32; s <<= 1) {
            int y = __shfl_up_sync(0xFFFFFFFFu, w, s);
            if (lane >= s) w += y;
        }
        if (lane < FS_T / 32) wsum[lane] = w;
    }
    __syncthreads();

    int run = x - local + (wid > 0 ? wsum[wid - 1] : 0);   // exclusive base
    #pragma unroll
    for (int j = 0; j < FS_CH; j++) {
        int i = base + j;
        if (i < M) {
            g_off[i] = run;
            g_pos[i] = run;
            g_cnt[i] = 0;          // re-zero for next replay
            run += c[j];
        }
    }
    if (tid == FS_T - 1) g_off[M] = wsum[FS_T / 32 - 1];
}

// ---------------------------------------------------------------------------
// Reorder edges into head-grouped records: rec = (bin<<16) | tail.
// ---------------------------------------------------------------------------
__global__ __launch_bounds__(256) void reorder_kernel(const void* __restrict__ trip, int E) {
    const int* p = (const int*)trip;
    int is64 = g_is64;
    int stride = is64 ? 6 : 3;
    int dt = is64 ? 2 : 1;
    int db = is64 ? 4 : 2;
    for (long e = blockIdx.x * blockDim.x + threadIdx.x; e < E;
         e += (long)gridDim.x * blockDim.x) {
        int h = p[e * stride];
        int t = p[e * stride + dt];
        int b = p[e * stride + db];
        int pos = atomicAdd(&g_pos[h], 1);
        g_rec[pos] = ((unsigned int)b << 16) | (unsigned int)t;
    }
}

// ---------------------------------------------------------------------------
// HMMA GEMM (fp16 hi/lo, fp32 accum -> fp32 parity). Unchanged from R13.
// ---------------------------------------------------------------------------
#define GBM 128
#define GBN 64
#define GKT 16

__device__ __forceinline__ void mma_f16(float* d, const uint32_t* a, const uint32_t* b) {
    asm volatile(
        "mma.sync.aligned.m16n8k16.row.col.f32.f16.f16.f32 "
        "{%0,%1,%2,%3}, {%4,%5,%6,%7}, {%8,%9}, {%0,%1,%2,%3};"
        : "+f"(d[0]), "+f"(d[1]), "+f"(d[2]), "+f"(d[3])
        : "r"(a[0]), "r"(a[1]), "r"(a[2]), "r"(a[3]), "r"(b[0]), "r"(b[1]));
}

__global__ __launch_bounds__(256) void gemm_hmma_kernel(
    const float* __restrict__ attn_b,   // [128]
    const float* __restrict__ aggr_b,   // [128]
    int M)
{
    __shared__ __half AsH[GBM][GKT];
    __shared__ __half AsL[GBM][GKT];
    __shared__ __half WsH[GBN][GKT];
    __shared__ __half WsL[GBN][GKT];

    int tid = threadIdx.x;
    int wid = tid >> 5, lane = tid & 31;
    int m0 = blockIdx.x * GBM;
    int region = blockIdx.y >> 1;
    int c0 = (blockIdx.y & 1) * GBN;
    int wrow0 = region * DIM + c0;

    int warpM = wid >> 1;
    int warpN = wid & 1;
    int g = lane >> 2;
    int t = lane & 3;

    float acc[2][4][4];
    #pragma unroll
    for (int mt = 0; mt < 2; mt++)
        #pragma unroll
        for (int nt = 0; nt < 4; nt++)
            #pragma unroll
            for (int r = 0; r < 4; r++) acc[mt][nt][r] = 0.f;

    for (int kt = 0; kt < DIM; kt += GKT) {
        #pragma unroll
        for (int j = 0; j < 4; j++) {
            int idx = tid + j * 256;
            int row = idx >> 3;
            int kc  = (idx & 7) * 2;
            int gr = m0 + row;
            uint32_t vh = 0, vl = 0;
            if (gr < M) {
                vh = *(const uint32_t*)(g_embH + (size_t)gr * DIM + kt + kc);
                vl = *(const uint32_t*)(g_embL + (size_t)gr * DIM + kt + kc);
            }
            *(uint32_t*)&AsH[row][kc] = vh;
            *(uint32_t*)&AsL[row][kc] = vl;
        }
        #pragma unroll
        for (int j = 0; j < 2; j++) {
            int idx = tid + j * 256;
            int col = idx >> 3;
            int kc  = (idx & 7) * 2;
            uint32_t vh = *(const uint32_t*)(g_WH + (size_t)(wrow0 + col) * DIM + kt + kc);
            uint32_t vl = *(const uint32_t*)(g_WL + (size_t)(wrow0 + col) * DIM + kt + kc);
            *(uint32_t*)&WsH[col][kc] = vh;
            *(uint32_t*)&WsL[col][kc] = vl;
        }
        __syncthreads();

        uint32_t aH[2][4], aL[2][4];
        #pragma unroll
        for (int mt = 0; mt < 2; mt++) {
            int rb = warpM * 32 + mt * 16;
            aH[mt][0] = *(const uint32_t*)&AsH[rb + g][2 * t];
            aH[mt][1] = *(const uint32_t*)&AsH[rb + g + 8][2 * t];
            aH[mt][2] = *(const uint32_t*)&AsH[rb + g][2 * t + 8];
            aH[mt][3] = *(const uint32_t*)&AsH[rb + g + 8][2 * t + 8];
            aL[mt][0] = *(const uint32_t*)&AsL[rb + g][2 * t];
            aL[mt][1] = *(const uint32_t*)&AsL[rb + g + 8][2 * t];
            aL[mt][2] = *(const uint32_t*)&AsL[rb + g][2 * t + 8];
            aL[mt][3] = *(const uint32_t*)&AsL[rb + g + 8][2 * t + 8];
        }
        uint32_t bH[4][2], bL[4][2];
        #pragma unroll
        for (int nt = 0; nt < 4; nt++) {
            int nb = warpN * 32 + nt * 8;
            bH[nt][0] = *(const uint32_t*)&WsH[nb + g][2 * t];
            bH[nt][1] = *(const uint32_t*)&WsH[nb + g][2 * t + 8];
            bL[nt][0] = *(const uint32_t*)&WsL[nb + g][2 * t];
            bL[nt][1] = *(const uint32_t*)&WsL[nb + g][2 * t + 8];
        }
        #pragma unroll
        for (int mt = 0; mt < 2; mt++)
            #pragma unroll
            for (int nt = 0; nt < 4; nt++) {
                mma_f16(acc[mt][nt], aH[mt], bH[nt]);
                mma_f16(acc[mt][nt], aL[mt], bH[nt]);
                mma_f16(acc[mt][nt], aH[mt], bL[nt]);
            }
        __syncthreads();
    }

    #pragma unroll
    for (int mt = 0; mt < 2; mt++) {
        #pragma unroll
        for (int rr = 0; rr < 2; rr++) {
            int gr = m0 + warpM * 32 + mt * 16 + g + rr * 8;
            if (gr >= M) continue;
            #pragma unroll
            for (int nt = 0; nt < 4; nt++) {
                int d = c0 + warpN * 32 + nt * 8 + t * 2;
                float v0 = acc[mt][nt][rr * 2 + 0];
                float v1 = acc[mt][nt][rr * 2 + 1];
                if (region == 0) {
                    g_A[(size_t)gr * DIM + d]     = v0 + attn_b[d];
                    g_A[(size_t)gr * DIM + d + 1] = v1 + attn_b[d + 1];
                } else if (region == 1) {
                    g_BM[(size_t)gr * 256 + (d >> 2) * 8 + (d & 3)]             = __float2half(v0);
                    g_BM[(size_t)gr * 256 + ((d + 1) >> 2) * 8 + ((d + 1) & 3)] = __float2half(v1);
                } else {
                    g_BM[(size_t)gr * 256 + (d >> 2) * 8 + 4 + (d & 3)] =
                        __float2half(v0 + aggr_b[d]);
                    g_BM[(size_t)gr * 256 + ((d + 1) >> 2) * 8 + 4 + ((d + 1) & 3)] =
                        __float2half(v1 + aggr_b[d + 1]);
                }
            }
        }
    }
}

// ---------------------------------------------------------------------------
// Fused per-relation aggregation: one warp per head relation.
// 4-edge groups with ONE-GROUP-AHEAD software pipeline: the next group's
// gathers are in flight while the current group computes.
// ---------------------------------------------------------------------------
struct EdgeVals { float2 b01, b23, m01, m23; };

__device__ __forceinline__ EdgeVals unpack_bm(uint4 raw) {
    EdgeVals ev;
    const __half2* hp = (const __half2*)&raw;
    ev.b01 = __half22float2(hp[0]);
    ev.b23 = __half22float2(hp[1]);
    ev.m01 = __half22float2(hp[2]);
    ev.m23 = __half22float2(hp[3]);
    return ev;
}

__global__ __launch_bounds__(256) void fused_aggr_kernel(
    const float* __restrict__ attn_bin,   // [10, 8]
    const float* __restrict__ attn_vec,   // [128]
    float* __restrict__ out,
    int M)
{
    __shared__ float lbin[16 * NUM_HEAD];
    if (threadIdx.x < 10 * NUM_HEAD)
        lbin[threadIdx.x] = leaky(attn_bin[threadIdx.x]);
    __syncthreads();

    int warp = blockIdx.x * (blockDim.x >> 5) + (threadIdx.x >> 5);
    int lane = threadIdx.x & 31;
    if (warp >= M) return;
    int h = warp;

    int e0 = g_off[h];
    int e1 = g_off[h + 1];
    int n  = e1 - e0;

    float4 a = *(const float4*)(g_A + (long)h * DIM + lane * 4);
    float4 v = *(const float4*)(attn_vec + lane * 4);
    int k = lane >> 2;

    const uint4* BMv = (const uint4*)g_BM;

    float4 acc = make_float4(0.f, 0.f, 0.f, 0.f);
    float ssum = 0.f;

    int egrp_end = e0 + (n & ~3);     // full 4-edge groups
    unsigned int r[4];
    uint4 raw[4];

    if (e0 < egrp_end) {
        #pragma unroll
        for (int j = 0; j < 4; j++) r[j] = __ldg(g_rec + e0 + j);
        #pragma unroll
        for (int j = 0; j < 4; j++)
            raw[j] = BMv[(size_t)(r[j] & 0xFFFFu) * 32 + lane];
    }

    for (int e = e0; e < egrp_end; e += 4) {
        // issue NEXT group's recs + gathers before computing current
        unsigned int rn[4];
        uint4 rawn[4];
        bool have_next = (e + 4) < egrp_end;
        if (have_next) {
            #pragma unroll
            for (int j = 0; j < 4; j++) rn[j] = __ldg(g_rec + e + 4 + j);
            #pragma unroll
            for (int j = 0; j < 4; j++)
                rawn[j] = BMv[(size_t)(rn[j] & 0xFFFFu) * 32 + lane];
        }

        float lb0 = lbin[(r[0] >> 16) * NUM_HEAD + k];
        float lb1 = lbin[(r[1] >> 16) * NUM_HEAD + k];
        float lb2 = lbin[(r[2] >> 16) * NUM_HEAD + k];
        float lb3 = lbin[(r[3] >> 16) * NUM_HEAD + k];

        EdgeVals ev0 = unpack_bm(raw[0]);
        EdgeVals ev1 = unpack_bm(raw[1]);
        EdgeVals ev2 = unpack_bm(raw[2]);
        EdgeVals ev3 = unpack_bm(raw[3]);

        float s0 = leaky(a.x + ev0.b01.x) * v.x + leaky(a.y + ev0.b01.y) * v.y
                 + leaky(a.z + ev0.b23.x) * v.z + leaky(a.w + ev0.b23.y) * v.w;
        float s1 = leaky(a.x + ev1.b01.x) * v.x + leaky(a.y + ev1.b01.y) * v.y
                 + leaky(a.z + ev1.b23.x) * v.z + leaky(a.w + ev1.b23.y) * v.w;
        float s2 = leaky(a.x + ev2.b01.x) * v.x + leaky(a.y + ev2.b01.y) * v.y
                 + leaky(a.z + ev2.b23.x) * v.z + leaky(a.w + ev2.b23.y) * v.w;
        float s3 = leaky(a.x + ev3.b01.x) * v.x + leaky(a.y + ev3.b01.y) * v.y
                 + leaky(a.z + ev3.b23.x) * v.z + leaky(a.w + ev3.b23.y) * v.w;

        float q0 = __shfl_xor_sync(0xFFFFFFFFu, s0, 1);
        float q1 = __shfl_xor_sync(0xFFFFFFFFu, s1, 1);
        float q2 = __shfl_xor_sync(0xFFFFFFFFu, s2, 1);
        float q3 = __shfl_xor_sync(0xFFFFFFFFu, s3, 1);
        s0 += q0; s1 += q1; s2 += q2; s3 += q3;
        q0 = __shfl_xor_sync(0xFFFFFFFFu, s0, 2);
        q1 = __shfl_xor_sync(0xFFFFFFFFu, s1, 2);
        q2 = __shfl_xor_sync(0xFFFFFFFFu, s2, 2);
        q3 = __shfl_xor_sync(0xFFFFFFFFu, s3, 2);
        s0 += q0; s1 += q1; s2 += q2; s3 += q3;

        float val0 = __expf(s0 + lb0);
        float val1 = __expf(s1 + lb1);
        float val2 = __expf(s2 + lb2);
        float val3 = __expf(s3 + lb3);

        acc.x += val0 * ev0.m01.x; acc.y += val0 * ev0.m01.y;
        acc.z += val0 * ev0.m23.x; acc.w += val0 * ev0.m23.y; ssum += val0;
        acc.x += val1 * ev1.m01.x; acc.y += val1 * ev1.m01.y;
        acc.z += val1 * ev1.m23.x; acc.w += val1 * ev1.m23.y; ssum += val1;
        acc.x += val2 * ev2.m01.x; acc.y += val2 * ev2.m01.y;
        acc.z += val2 * ev2.m23.x; acc.w += val2 * ev2.m23.y; ssum += val2;
        acc.x += val3 * ev3.m01.x; acc.y += val3 * ev3.m01.y;
        acc.z += val3 * ev3.m23.x; acc.w += val3 * ev3.m23.y; ssum += val3;

        if (have_next) {
            #pragma unroll
            for (int j = 0; j < 4; j++) { r[j] = rn[j]; raw[j] = rawn[j]; }
        }
    }

    // tail (<4 edges)
    for (int e = egrp_end; e < e1; e++) {
        unsigned int rec = __ldg(g_rec + e);
        int t = rec & 0xFFFFu, b = rec >> 16;
        uint4 rw = BMv[(size_t)t * 32 + lane];
        EdgeVals ev = unpack_bm(rw);

        float s = leaky(a.x + ev.b01.x) * v.x + leaky(a.y + ev.b01.y) * v.y
                + leaky(a.z + ev.b23.x) * v.z + leaky(a.w + ev.b23.y) * v.w;
        s += __shfl_xor_sync(0xFFFFFFFFu, s, 1);
        s += __shfl_xor_sync(0xFFFFFFFFu, s, 2);

        float val = __expf(s + lbin[b * NUM_HEAD + k]);
        acc.x += val * ev.m01.x; acc.y += val * ev.m01.y;
        acc.z += val * ev.m23.x; acc.w += val * ev.m23.y; ssum += val;
    }

    float inv = __frcp_rn(ssum + 1e-16f);
    *(float4*)(out + (long)h * DIM + lane * 4) =
        make_float4(acc.x * inv, acc.y * inv, acc.z * inv, acc.w * inv);
}

// ---------------------------------------------------------------------------
extern "C" void kernel_launch(void* const* d_in, const int* in_sizes, int n_in,
                              void* d_out, int out_size)
{
    const float* emb      = (const float*)d_in[0];
    const void*  trip     = (const void*)d_in[1];
    const float* attn_w   = (const float*)d_in[2];
    const float* attn_b   = (const float*)d_in[3];
    const float* attn_bin = (const float*)d_in[4];
    const float* attn_vec = (const float*)d_in[5];
    const float* aggr_w   = (const float*)d_in[6];
    const float* aggr_b   = (const float*)d_in[7];
    float*       out      = (float*)d_out;

    int M = in_sizes[0] / DIM;        // 20000
    int E = in_sizes[1] / 3;          // 640000

    static cudaStream_t s_gemm = nullptr;
    static cudaEvent_t ev_fork = nullptr, ev_join = nullptr;
    if (s_gemm == nullptr) {
        cudaStreamCreateWithFlags(&s_gemm, cudaStreamNonBlocking);
        cudaEventCreateWithFlags(&ev_fork, cudaEventDisableTiming);
        cudaEventCreateWithFlags(&ev_join, cudaEventDisableTiming);
    }

    // Fork: hi/lo conversion + HMMA GEMM on the side stream.
    cudaEventRecord(ev_fork, 0);
    cudaStreamWaitEvent(s_gemm, ev_fork, 0);

    conv_emb_kernel<<<592, 256, 0, s_gemm>>>(emb, M * DIM);
    conv_w_kernel<<<(384 * DIM + 255) / 256, 256, 0, s_gemm>>>(attn_w, aggr_w);
    dim3 ggrid((M + GBM - 1) / GBM, 6);
    gemm_hmma_kernel<<<ggrid, 256, 0, s_gemm>>>(attn_b, aggr_b, M);
    cudaEventRecord(ev_join, s_gemm);

    // Main stream: counting sort by head (3 kernels now).
    hist_kernel<<<592, 256>>>(trip, E);
    fullscan_kernel<<<1, FS_T>>>(M);
    reorder_kernel<<<592, 256>>>(trip, E);

    // Join: fused aggregation needs tables + sorted edges.
    cudaStreamWaitEvent(0, ev_join, 0);

    int warps_per_block = 256 / 32;
    int nblocks = (M + warps_per_block - 1) / warps_per_block;
    fused_aggr_kernel<<<nblocks, 256>>>(attn_bin, attn_vec, out, M);
}

// round 15
// speedup vs baseline: 1.1070x; 1.1070x over previous
#include <cuda_runtime.h>
#include <cuda_fp16.h>
#include <cstdint>

#define NUM_REL_MAX   20000
#define NUM_EDGES_MAX 640000
#define DIM           128
#define NUM_HEAD      8
#define NEG_SLOPE     0.2f
#define SCAN_B        256
#define MAX_BLKS      ((NUM_REL_MAX + SCAN_B - 1) / SCAN_B)   // 79

// Scratch (device globals -- no allocation allowed)
__device__ float  g_A[NUM_REL_MAX * DIM];          // emb @ W1^T + attn_bias (fp32)
// Interleaved fp16 table: per relation row of 256 halves (512 B).
// Quad q at byte offset q*16: [B[4q..4q+3] | MSG[4q..4q+3]]
__device__ __half g_BM[NUM_REL_MAX * 2 * DIM];
__device__ __half g_embH[NUM_REL_MAX * DIM];       // emb hi (fp16)
__device__ __half g_embL[NUM_REL_MAX * DIM];       // emb lo (fp16 residual)
__device__ __half g_WH[384 * DIM];                 // combined weights hi
__device__ __half g_WL[384 * DIM];                 // combined weights lo
__device__ int    g_cnt[NUM_REL_MAX];              // zero at start; re-zeroed by scan1
__device__ int    g_off[NUM_REL_MAX + 1];
__device__ int    g_pos[NUM_REL_MAX];
__device__ int    g_blk[MAX_BLKS + 1];
__device__ unsigned int g_rec[NUM_EDGES_MAX];      // packed (bin<<16)|tail
__device__ int    g_is64;

__device__ __forceinline__ float leaky(float x) {
    return x >= 0.0f ? x : NEG_SLOPE * x;
}

// ---------------------------------------------------------------------------
// hi/lo fp16 split of emb (once; GEMM mainloop then has no conversions).
// ---------------------------------------------------------------------------
__global__ __launch_bounds__(256) void conv_emb_kernel(const float* __restrict__ emb, int n) {
    for (int i = blockIdx.x * blockDim.x + threadIdx.x; i < n;
         i += gridDim.x * blockDim.x) {
        float x = emb[i];
        __half h = __float2half(x);
        g_embH[i] = h;
        g_embL[i] = __float2half(x - __half2float(h));
    }
}

// Combined weight matrix Wc[384][128] hi/lo.
__global__ __launch_bounds__(256) void conv_w_kernel(
    const float* __restrict__ attn_w, const float* __restrict__ aggr_w) {
    int idx = blockIdx.x * blockDim.x + threadIdx.x;
    if (idx >= 384 * DIM) return;
    int r = idx >> 7, c = idx & 127;
    float x = (r < 128)  ? attn_w[r * 256 + c]
            : (r < 256)  ? attn_w[(r - 128) * 256 + 128 + c]
                         : aggr_w[(r - 256) * 128 + c];
    __half h = __float2half(x);
    g_WH[idx] = h;
    g_WL[idx] = __float2half(x - __half2float(h));
}

// ---------------------------------------------------------------------------
// Per-block dtype sniff: int64 triplets (values < 2^31) have zero odd words.
// ---------------------------------------------------------------------------
__device__ __forceinline__ int sniff_is64(const unsigned int* trip_w) {
    unsigned int w = 0;
    int lane = threadIdx.x & 31;
    if (threadIdx.x < 32) w = trip_w[1 + 2 * lane];   // odd words 1..63
    unsigned int ball = __ballot_sync(0xFFFFFFFFu, w != 0u);
    return ball == 0u;   // valid in warp 0
}

// ---------------------------------------------------------------------------
// Histogram of head indices (dtype detected in-kernel; block 0 publishes it).
// g_cnt must be zero on entry (static init; re-zeroed by scan1 each replay).
// ---------------------------------------------------------------------------
__global__ __launch_bounds__(256) void hist_kernel(const void* __restrict__ trip, int E) {
    __shared__ int s_is64;
    int is64w = sniff_is64((const unsigned int*)trip);
    if (threadIdx.x == 0) {
        s_is64 = is64w;
        if (blockIdx.x == 0) g_is64 = is64w;
    }
    __syncthreads();
    const int* p = (const int*)trip;
    int stride = s_is64 ? 6 : 3;
    for (long e = blockIdx.x * blockDim.x + threadIdx.x; e < E;
         e += (long)gridDim.x * blockDim.x) {
        int h = p[e * stride];
        atomicAdd(&g_cnt[h], 1);
    }
}

// ---------------------------------------------------------------------------
// Hierarchical scan stage 1: per-block (256-elem) exclusive scan.
// Re-zeroes g_cnt (read-then-clear) to preserve the replay invariant.
// ---------------------------------------------------------------------------
__global__ __launch_bounds__(SCAN_B) void scan1_kernel(int M) {
    __shared__ int wsum[SCAN_B / 32];
    int tid = threadIdx.x;
    int lane = tid & 31;
    int wid = tid >> 5;
    int i = blockIdx.x * SCAN_B + tid;
    int v = (i < M) ? g_cnt[i] : 0;
    if (i < M) g_cnt[i] = 0;      // re-zero for the next graph replay

    int x = v;
    #pragma unroll
    for (int s = 1; s < 32; s <<= 1) {
        int y = __shfl_up_sync(0xFFFFFFFFu, x, s);
        if (lane >= s) x += y;
    }
    if (lane == 31) wsum[wid] = x;
    __syncthreads();
    if (wid == 0) {
        int w = (lane < SCAN_B / 32) ? wsum[lane] : 0;
        #pragma unroll
        for (int s = 1; s < SCAN_B / 32; s <<= 1) {
            int y = __shfl_up_sync(0xFFFFFFFFu, w, s);
            if (lane >= s) w += y;
        }
        if (lane < SCAN_B / 32) wsum[lane] = w;
    }
    __syncthreads();
    int excl = x - v + (wid > 0 ? wsum[wid - 1] : 0);
    if (i < M) g_off[i] = excl;
    if (tid == SCAN_B - 1) g_blk[blockIdx.x] = excl + v;
}

// ---------------------------------------------------------------------------
// Stage 2: one warp scans block sums (nblk <= 96).
// ---------------------------------------------------------------------------
__global__ void scan2_kernel(int nblk, int M) {
    int lane = threadIdx.x;
    int vals[3];
    int total = 0;
    #pragma unroll
    for (int ch = 0; ch < 3; ch++) {
        int i = ch * 32 + lane;
        int v = (i < nblk) ? g_blk[i] : 0;
        int x = v;
        #pragma unroll
        for (int s = 1; s < 32; s <<= 1) {
            int y = __shfl_up_sync(0xFFFFFFFFu, x, s);
            if (lane >= s) x += y;
        }
        vals[ch] = x - v + total;
        total += __shfl_sync(0xFFFFFFFFu, x, 31);
    }
    #pragma unroll
    for (int ch = 0; ch < 3; ch++) {
        int i = ch * 32 + lane;
        if (i < nblk) g_blk[i] = vals[ch];
    }
    if (lane == 0) g_off[M] = total;
}

// ---------------------------------------------------------------------------
// Stage 3: add block offsets; copy to g_pos.
// ---------------------------------------------------------------------------
__global__ __launch_bounds__(SCAN_B) void scan3_kernel(int M) {
    int i = blockIdx.x * SCAN_B + threadIdx.x;
    if (i < M) {
        int o = g_off[i] + g_blk[blockIdx.x];
        g_off[i] = o;
        g_pos[i] = o;
    }
}

// ---------------------------------------------------------------------------
// Reorder edges into head-grouped records: rec = (bin<<16) | tail.
// ---------------------------------------------------------------------------
__global__ __launch_bounds__(256) void reorder_kernel(const void* __restrict__ trip, int E) {
    const int* p = (const int*)trip;
    int is64 = g_is64;
    int stride = is64 ? 6 : 3;
    int dt = is64 ? 2 : 1;
    int db = is64 ? 4 : 2;
    for (long e = blockIdx.x * blockDim.x + threadIdx.x; e < E;
         e += (long)gridDim.x * blockDim.x) {
        int h = p[e * stride];
        int t = p[e * stride + dt];
        int b = p[e * stride + db];
        int pos = atomicAdd(&g_pos[h], 1);
        g_rec[pos] = ((unsigned int)b << 16) | (unsigned int)t;
    }
}

// ---------------------------------------------------------------------------
// HMMA GEMM (fp16 hi/lo, fp32 accum -> fp32 parity). Unchanged from R13.
// ---------------------------------------------------------------------------
#define GBM 128
#define GBN 64
#define GKT 16

__device__ __forceinline__ void mma_f16(float* d, const uint32_t* a, const uint32_t* b) {
    asm volatile(
        "mma.sync.aligned.m16n8k16.row.col.f32.f16.f16.f32 "
        "{%0,%1,%2,%3}, {%4,%5,%6,%7}, {%8,%9}, {%0,%1,%2,%3};"
        : "+f"(d[0]), "+f"(d[1]), "+f"(d[2]), "+f"(d[3])
        : "r"(a[0]), "r"(a[1]), "r"(a[2]), "r"(a[3]), "r"(b[0]), "r"(b[1]));
}

__global__ __launch_bounds__(256) void gemm_hmma_kernel(
    const float* __restrict__ attn_b,   // [128]
    const float* __restrict__ aggr_b,   // [128]
    int M)
{
    __shared__ __half AsH[GBM][GKT];
    __shared__ __half AsL[GBM][GKT];
    __shared__ __half WsH[GBN][GKT];
    __shared__ __half WsL[GBN][GKT];

    int tid = threadIdx.x;
    int wid = tid >> 5, lane = tid & 31;
    int m0 = blockIdx.x * GBM;
    int region = blockIdx.y >> 1;
    int c0 = (blockIdx.y & 1) * GBN;
    int wrow0 = region * DIM + c0;

    int warpM = wid >> 1;
    int warpN = wid & 1;
    int g = lane >> 2;
    int t = lane & 3;

    float acc[2][4][4];
    #pragma unroll
    for (int mt = 0; mt < 2; mt++)
        #pragma unroll
        for (int nt = 0; nt < 4; nt++)
            #pragma unroll
            for (int r = 0; r < 4; r++) acc[mt][nt][r] = 0.f;

    for (int kt = 0; kt < DIM; kt += GKT) {
        #pragma unroll
        for (int j = 0; j < 4; j++) {
            int idx = tid + j * 256;
            int row = idx >> 3;
            int kc  = (idx & 7) * 2;
            int gr = m0 + row;
            uint32_t vh = 0, vl = 0;
            if (gr < M) {
                vh = *(const uint32_t*)(g_embH + (size_t)gr * DIM + kt + kc);
                vl = *(const uint32_t*)(g_embL + (size_t)gr * DIM + kt + kc);
            }
            *(uint32_t*)&AsH[row][kc] = vh;
            *(uint32_t*)&AsL[row][kc] = vl;
        }
        #pragma unroll
        for (int j = 0; j < 2; j++) {
            int idx = tid + j * 256;
            int col = idx >> 3;
            int kc  = (idx & 7) * 2;
            uint32_t vh = *(const uint32_t*)(g_WH + (size_t)(wrow0 + col) * DIM + kt + kc);
            uint32_t vl = *(const uint32_t*)(g_WL + (size_t)(wrow0 + col) * DIM + kt + kc);
            *(uint32_t*)&WsH[col][kc] = vh;
            *(uint32_t*)&WsL[col][kc] = vl;
        }
        __syncthreads();

        uint32_t aH[2][4], aL[2][4];
        #pragma unroll
        for (int mt = 0; mt < 2; mt++) {
            int rb = warpM * 32 + mt * 16;
            aH[mt][0] = *(const uint32_t*)&AsH[rb + g][2 * t];
            aH[mt][1] = *(const uint32_t*)&AsH[rb + g + 8][2 * t];
            aH[mt][2] = *(const uint32_t*)&AsH[rb + g][2 * t + 8];
            aH[mt][3] = *(const uint32_t*)&AsH[rb + g + 8][2 * t + 8];
            aL[mt][0] = *(const uint32_t*)&AsL[rb + g][2 * t];
            aL[mt][1] = *(const uint32_t*)&AsL[rb + g + 8][2 * t];
            aL[mt][2] = *(const uint32_t*)&AsL[rb + g][2 * t + 8];
            aL[mt][3] = *(const uint32_t*)&AsL[rb + g + 8][2 * t + 8];
        }
        uint32_t bH[4][2], bL[4][2];
        #pragma unroll
        for (int nt = 0; nt < 4; nt++) {
            int nb = warpN * 32 + nt * 8;
            bH[nt][0] = *(const uint32_t*)&WsH[nb + g][2 * t];
            bH[nt][1] = *(const uint32_t*)&WsH[nb + g][2 * t + 8];
            bL[nt][0] = *(const uint32_t*)&WsL[nb + g][2 * t];
            bL[nt][1] = *(const uint32_t*)&WsL[nb + g][2 * t + 8];
        }
        #pragma unroll
        for (int mt = 0; mt < 2; mt++)
            #pragma unroll
            for (int nt = 0; nt < 4; nt++) {
                mma_f16(acc[mt][nt], aH[mt], bH[nt]);
                mma_f16(acc[mt][nt], aL[mt], bH[nt]);
                mma_f16(acc[mt][nt], aH[mt], bL[nt]);
            }
        __syncthreads();
    }

    #pragma unroll
    for (int mt = 0; mt < 2; mt++) {
        #pragma unroll
        for (int rr = 0; rr < 2; rr++) {
            int gr = m0 + warpM * 32 + mt * 16 + g + rr * 8;
            if (gr >= M) continue;
            #pragma unroll
            for (int nt = 0; nt < 4; nt++) {
                int d = c0 + warpN * 32 + nt * 8 + t * 2;
                float v0 = acc[mt][nt][rr * 2 + 0];
                float v1 = acc[mt][nt][rr * 2 + 1];
                if (region == 0) {
                    g_A[(size_t)gr * DIM + d]     = v0 + attn_b[d];
                    g_A[(size_t)gr * DIM + d + 1] = v1 + attn_b[d + 1];
                } else if (region == 1) {
                    g_BM[(size_t)gr * 256 + (d >> 2) * 8 + (d & 3)]             = __float2half(v0);
                    g_BM[(size_t)gr * 256 + ((d + 1) >> 2) * 8 + ((d + 1) & 3)] = __float2half(v1);
                } else {
                    g_BM[(size_t)gr * 256 + (d >> 2) * 8 + 4 + (d & 3)] =
                        __float2half(v0 + aggr_b[d]);
                    g_BM[(size_t)gr * 256 + ((d + 1) >> 2) * 8 + 4 + ((d + 1) & 3)] =
                        __float2half(v1 + aggr_b[d + 1]);
                }
            }
        }
    }
}

// ---------------------------------------------------------------------------
// Fused per-relation aggregation (proven R12/R13 body: 4-edge unroll with
// rolling 4-deep rec prefetch, single gather wave per group).
// ---------------------------------------------------------------------------
struct EdgeVals { float2 b01, b23, m01, m23; };

__device__ __forceinline__ EdgeVals unpack_bm(uint4 raw) {
    EdgeVals ev;
    const __half2* hp = (const __half2*)&raw;
    ev.b01 = __half22float2(hp[0]);
    ev.b23 = __half22float2(hp[1]);
    ev.m01 = __half22float2(hp[2]);
    ev.m23 = __half22float2(hp[3]);
    return ev;
}

__global__ __launch_bounds__(256) void fused_aggr_kernel(
    const float* __restrict__ attn_bin,   // [10, 8]
    const float* __restrict__ attn_vec,   // [128]
    float* __restrict__ out,
    int M)
{
    __shared__ float lbin[16 * NUM_HEAD];
    if (threadIdx.x < 10 * NUM_HEAD)
        lbin[threadIdx.x] = leaky(attn_bin[threadIdx.x]);
    __syncthreads();

    int warp = blockIdx.x * (blockDim.x >> 5) + (threadIdx.x >> 5);
    int lane = threadIdx.x & 31;
    if (warp >= M) return;
    int h = warp;

    int e0 = g_off[h];
    int e1 = g_off[h + 1];

    float4 a = *(const float4*)(g_A + (long)h * DIM + lane * 4);
    float4 v = *(const float4*)(attn_vec + lane * 4);
    int k = lane >> 2;

    const uint4* BMv = (const uint4*)g_BM;

    float4 acc = make_float4(0.f, 0.f, 0.f, 0.f);
    float ssum = 0.f;

    unsigned int r0 = 0, r1 = 0, r2 = 0, r3 = 0;
    int n = e1 - e0;
    if (n > 0) r0 = __ldg(g_rec + e0);
    if (n > 1) r1 = __ldg(g_rec + e0 + 1);
    if (n > 2) r2 = __ldg(g_rec + e0 + 2);
    if (n > 3) r3 = __ldg(g_rec + e0 + 3);

    int e = e0;
    while (e + 3 < e1) {
        int t0 = r0 & 0xFFFFu, b0 = r0 >> 16;
        int t1 = r1 & 0xFFFFu, b1 = r1 >> 16;
        int t2 = r2 & 0xFFFFu, b2 = r2 >> 16;
        int t3 = r3 & 0xFFFFu, b3 = r3 >> 16;
        if (e + 4 < e1) r0 = __ldg(g_rec + e + 4);
        if (e + 5 < e1) r1 = __ldg(g_rec + e + 5);
        if (e + 6 < e1) r2 = __ldg(g_rec + e + 6);
        if (e + 7 < e1) r3 = __ldg(g_rec + e + 7);

        uint4 raw0 = BMv[(size_t)t0 * 32 + lane];
        uint4 raw1 = BMv[(size_t)t1 * 32 + lane];
        uint4 raw2 = BMv[(size_t)t2 * 32 + lane];
        uint4 raw3 = BMv[(size_t)t3 * 32 + lane];
        float lb0 = lbin[b0 * NUM_HEAD + k];
        float lb1 = lbin[b1 * NUM_HEAD + k];
        float lb2 = lbin[b2 * NUM_HEAD + k];
        float lb3 = lbin[b3 * NUM_HEAD + k];

        EdgeVals ev0 = unpack_bm(raw0);
        EdgeVals ev1 = unpack_bm(raw1);
        EdgeVals ev2 = unpack_bm(raw2);
        EdgeVals ev3 = unpack_bm(raw3);

        float s0 = leaky(a.x + ev0.b01.x) * v.x + leaky(a.y + ev0.b01.y) * v.y
                 + leaky(a.z + ev0.b23.x) * v.z + leaky(a.w + ev0.b23.y) * v.w;
        float s1 = leaky(a.x + ev1.b01.x) * v.x + leaky(a.y + ev1.b01.y) * v.y
                 + leaky(a.z + ev1.b23.x) * v.z + leaky(a.w + ev1.b23.y) * v.w;
        float s2 = leaky(a.x + ev2.b01.x) * v.x + leaky(a.y + ev2.b01.y) * v.y
                 + leaky(a.z + ev2.b23.x) * v.z + leaky(a.w + ev2.b23.y) * v.w;
        float s3 = leaky(a.x + ev3.b01.x) * v.x + leaky(a.y + ev3.b01.y) * v.y
                 + leaky(a.z + ev3.b23.x) * v.z + leaky(a.w + ev3.b23.y) * v.w;

        float q0 = __shfl_xor_sync(0xFFFFFFFFu, s0, 1);
        float q1 = __shfl_xor_sync(0xFFFFFFFFu, s1, 1);
        float q2 = __shfl_xor_sync(0xFFFFFFFFu, s2, 1);
        float q3 = __shfl_xor_sync(0xFFFFFFFFu, s3, 1);
        s0 += q0; s1 += q1; s2 += q2; s3 += q3;
        q0 = __shfl_xor_sync(0xFFFFFFFFu, s0, 2);
        q1 = __shfl_xor_sync(0xFFFFFFFFu, s1, 2);
        q2 = __shfl_xor_sync(0xFFFFFFFFu, s2, 2);
        q3 = __shfl_xor_sync(0xFFFFFFFFu, s3, 2);
        s0 += q0; s1 += q1; s2 += q2; s3 += q3;

        float val0 = __expf(s0 + lb0);
        float val1 = __expf(s1 + lb1);
        float val2 = __expf(s2 + lb2);
        float val3 = __expf(s3 + lb3);

        acc.x += val0 * ev0.m01.x; acc.y += val0 * ev0.m01.y;
        acc.z += val0 * ev0.m23.x; acc.w += val0 * ev0.m23.y; ssum += val0;
        acc.x += val1 * ev1.m01.x; acc.y += val1 * ev1.m01.y;
        acc.z += val1 * ev1.m23.x; acc.w += val1 * ev1.m23.y; ssum += val1;
        acc.x += val2 * ev2.m01.x; acc.y += val2 * ev2.m01.y;
        acc.z += val2 * ev2.m23.x; acc.w += val2 * ev2.m23.y; ssum += val2;
        acc.x += val3 * ev3.m01.x; acc.y += val3 * ev3.m01.y;
        acc.z += val3 * ev3.m23.x; acc.w += val3 * ev3.m23.y; ssum += val3;

        e += 4;
    }

    for (; e < e1; e++) {
        unsigned int rec = __ldg(g_rec + e);
        int t = rec & 0xFFFFu, b = rec >> 16;
        uint4 raw = BMv[(size_t)t * 32 + lane];
        EdgeVals ev = unpack_bm(raw);

        float s = leaky(a.x + ev.b01.x) * v.x + leaky(a.y + ev.b01.y) * v.y
                + leaky(a.z + ev.b23.x) * v.z + leaky(a.w + ev.b23.y) * v.w;
        s += __shfl_xor_sync(0xFFFFFFFFu, s, 1);
        s += __shfl_xor_sync(0xFFFFFFFFu, s, 2);

        float val = __expf(s + lbin[b * NUM_HEAD + k]);
        acc.x += val * ev.m01.x; acc.y += val * ev.m01.y;
        acc.z += val * ev.m23.x; acc.w += val * ev.m23.y; ssum += val;
    }

    float inv = __frcp_rn(ssum + 1e-16f);
    *(float4*)(out + (long)h * DIM + lane * 4) =
        make_float4(acc.x * inv, acc.y * inv, acc.z * inv, acc.w * inv);
}

// ---------------------------------------------------------------------------
extern "C" void kernel_launch(void* const* d_in, const int* in_sizes, int n_in,
                              void* d_out, int out_size)
{
    const float* emb      = (const float*)d_in[0];
    const void*  trip     = (const void*)d_in[1];
    const float* attn_w   = (const float*)d_in[2];
    const float* attn_b   = (const float*)d_in[3];
    const float* attn_bin = (const float*)d_in[4];
    const float* attn_vec = (const float*)d_in[5];
    const float* aggr_w   = (const float*)d_in[6];
    const float* aggr_b   = (const float*)d_in[7];
    float*       out      = (float*)d_out;

    int M = in_sizes[0] / DIM;        // 20000
    int E = in_sizes[1] / 3;          // 640000
    int nblk = (M + SCAN_B - 1) / SCAN_B;

    static cudaStream_t s_gemm = nullptr;
    static cudaEvent_t ev_fork = nullptr, ev_join = nullptr;
    if (s_gemm == nullptr) {
        cudaStreamCreateWithFlags(&s_gemm, cudaStreamNonBlocking);
        cudaEventCreateWithFlags(&ev_fork, cudaEventDisableTiming);
        cudaEventCreateWithFlags(&ev_join, cudaEventDisableTiming);
    }

    // Fork: hi/lo conversion + HMMA GEMM on the side stream.
    cudaEventRecord(ev_fork, 0);
    cudaStreamWaitEvent(s_gemm, ev_fork, 0);

    conv_emb_kernel<<<592, 256, 0, s_gemm>>>(emb, M * DIM);
    conv_w_kernel<<<(384 * DIM + 255) / 256, 256, 0, s_gemm>>>(attn_w, aggr_w);
    dim3 ggrid((M + GBM - 1) / GBM, 6);
    gemm_hmma_kernel<<<ggrid, 256, 0, s_gemm>>>(attn_b, aggr_b, M);
    cudaEventRecord(ev_join, s_gemm);

    // Main stream: counting sort by head.
    hist_kernel<<<592, 256>>>(trip, E);
    scan1_kernel<<<nblk, SCAN_B>>>(M);
    scan2_kernel<<<1, 32>>>(nblk, M);
    scan3_kernel<<<nblk, SCAN_B>>>(M);
    reorder_kernel<<<592, 256>>>(trip, E);

    // Join: fused aggregation needs tables + sorted edges.
    cudaStreamWaitEvent(0, ev_join, 0);

    int warps_per_block = 256 / 32;
    int nblocks = (M + warps_per_block - 1) / warps_per_block;
    fused_aggr_kernel<<<nblocks, 256>>>(attn_bin, attn_vec, out, M);
}